// round 4
// baseline (speedup 1.0000x reference)
#include <cuda_runtime.h>

// MorphologicalDegradation, i=30 fixed: k=7 circular SE, dilation, weight=0.24.
//   out = clip(0.76*x + 0.24*(1 - prod_taps(1 - x_shift)), 0, 1)
// Row decomposition (half-widths by dy): {0,2,2,3,2,2,0}:
//   out(y) = f( t(y-3) * h2(y-2) * h2(y-1) * h3(y) * h2(y+1) * h2(y+2) * t(y+3) )
// R4: issue-bound per R3 profile (occ 37.6%, issue 47.6%, no pipe saturated).
// Switch mul-heavy body to packed f32x2 (FFMA2/FMUL2 via inline PTX) to halve
// fma-pipe instruction count. Rows loaded as ulonglong2 -> aligned f32 pairs free.

#include <cstdint>
typedef unsigned long long u64;

#define MUL2(d,a,b)    asm("mul.rn.f32x2 %0, %1, %2;"     : "=l"(d) : "l"(a), "l"(b))
#define FMA2(d,a,b,c)  asm("fma.rn.f32x2 %0, %1, %2, %3;" : "=l"(d) : "l"(a), "l"(b), "l"(c))
#define PACK2F(d,lo,hi)   asm("mov.b64 %0, {%1, %2};" : "=l"(d) : "f"(lo), "f"(hi))
#define UNPACK2F(lo,hi,s) asm("mov.b64 {%0, %1}, %2;" : "=f"(lo), "=f"(hi) : "l"(s))

static constexpr int Hh   = 512;
static constexpr int Ww   = 512;
static constexpr int ROUT = 8;             // output rows per warp-chunk
static constexpr int ITERS = ROUT + 6;     // 14 input rows streamed

struct Row { u64 L0, L1, M0, M1, R0, R1; };  // cols c0-4.. | c0.. | c0+4.. as f32 pairs

__device__ __forceinline__ Row load_row(const float* base, int r, int c0)
{
    Row w;
    if ((unsigned)r < (unsigned)Hh) {
        const float* row = base + r * Ww;
        ulonglong2 m = *(const ulonglong2*)(row + c0);
        w.M0 = m.x; w.M1 = m.y;
        if (c0 >= 4) { ulonglong2 l = *(const ulonglong2*)(row + c0 - 4); w.L0 = l.x; w.L1 = l.y; }
        else         { w.L0 = 0ULL; w.L1 = 0ULL; }
        if (c0 <= Ww - 8) { ulonglong2 rr = *(const ulonglong2*)(row + c0 + 4); w.R0 = rr.x; w.R1 = rr.y; }
        else              { w.R0 = 0ULL; w.R1 = 0ULL; }
    } else {
        w.L0 = w.L1 = w.M0 = w.M1 = w.R0 = w.R1 = 0ULL;  // zero pad -> t = 1 (no-op factor)
    }
    return w;
}

__global__ void __launch_bounds__(256, 4)
morph_kernel(const float* __restrict__ x, float* __restrict__ out)
{
    const int gt    = blockIdx.x * 256 + threadIdx.x;
    const int gw    = gt >> 5;          // global warp id, 0..4095
    const int ln    = gt & 31;
    const int wp    = gw & 3;           // column quadrant (128 cols each)
    const int chunk = (gw >> 2) & 63;   // row chunk, 64 chunks of 8 rows
    const int img   = gw >> 8;          // 16 images

    const int c0 = wp * 128 + ln * 4;   // first of 4 owned columns
    const int y0 = chunk * ROUT;

    const float* base  = x   + img * (Hh * Ww);
    float*       obase = out + img * (Hh * Ww);

    u64 ONE2, NEG2, W2, IW2;
    PACK2F(ONE2, 1.0f, 1.0f);
    PACK2F(NEG2, -1.0f, -1.0f);
    PACK2F(W2, 0.24f, 0.24f);
    PACK2F(IW2, 0.76f, 0.76f);

    u64 accA[7], accB[7];   // rotating accumulators: A = cols 0,1  B = cols 2,3

    Row cur = load_row(base, y0 - 3, c0);

#pragma unroll
    for (int ii = 0; ii < ITERS; ++ii) {
        // prefetch next input row (depth 1)
        Row nxt;
        if (ii + 1 < ITERS) nxt = load_row(base, y0 - 2 + ii, c0);
        else { nxt.L0 = nxt.L1 = nxt.M0 = nxt.M1 = nxt.R0 = nxt.R1 = 0ULL; }

        // t = 1 - x, packed; T0=(t0,t1) T1=(t2,t3) T2=(t4,t5) T3=(t6,t7) T4=(t8,t9) T5=(t10,t11)
        u64 T0, T1, T2, T3, T4, T5;
        FMA2(T0, cur.L0, NEG2, ONE2);
        FMA2(T1, cur.L1, NEG2, ONE2);
        FMA2(T2, cur.M0, NEG2, ONE2);
        FMA2(T3, cur.M1, NEG2, ONE2);
        FMA2(T4, cur.R0, NEG2, ONE2);
        FMA2(T5, cur.R1, NEG2, ONE2);

        // scalar halves for shifted pairs
        float t0d, t1, t2, t3, t4, t5, t6, t7, t8, t9, t10, t11d;
        UNPACK2F(t0d, t1, T0);
        UNPACK2F(t2,  t3, T1);
        UNPACK2F(t4,  t5, T2);
        UNPACK2F(t6,  t7, T3);
        UNPACK2F(t8,  t9, T4);
        UNPACK2F(t10, t11d, T5);
        (void)t0d; (void)t11d;

        u64 S12, S34, S56, S78, S910;
        PACK2F(S12,  t1, t2);
        PACK2F(S34,  t3, t4);
        PACK2F(S56,  t5, t6);
        PACK2F(S78,  t7, t8);
        PACK2F(S910, t9, t10);

        // h2A=(h2[0],h2[1]) = T1*S34*[T2*S56*T3];  h2B=(h2[2],h2[3]) = S78*T4*[T2*S56*T3]
        u64 com, h2A, h2B, h3A, h3B;
        MUL2(com, T2, S56);  MUL2(com, com, T3);
        MUL2(h2A, T1, S34);  MUL2(h2A, h2A, com);
        MUL2(h2B, S78, T4);  MUL2(h2B, h2B, com);
        MUL2(h3A, h2A, S12); MUL2(h3A, h3A, S78);   // h3 = h2 * t(c-3) * t(c+3)
        MUL2(h3B, h2B, S34); MUL2(h3B, h3B, S910);

        // rotating accumulators; slot indices static after unroll
        accA[ii % 7] = T2;  accB[ii % 7] = T3;                               // d=0: t (dy=-3)
        MUL2(accA[(ii + 6) % 7], accA[(ii + 6) % 7], h2A);                   // d=1: h2 (dy=-2)
        MUL2(accB[(ii + 6) % 7], accB[(ii + 6) % 7], h2B);
        MUL2(accA[(ii + 5) % 7], accA[(ii + 5) % 7], h2A);                   // d=2: h2 (dy=-1)
        MUL2(accB[(ii + 5) % 7], accB[(ii + 5) % 7], h2B);
        MUL2(accA[(ii + 4) % 7], accA[(ii + 4) % 7], h3A);                   // d=3: h3 (dy=0)
        MUL2(accB[(ii + 4) % 7], accB[(ii + 4) % 7], h3B);
        MUL2(accA[(ii + 3) % 7], accA[(ii + 3) % 7], h2A);                   // d=4: h2 (dy=+1)
        MUL2(accB[(ii + 3) % 7], accB[(ii + 3) % 7], h2B);
        MUL2(accA[(ii + 2) % 7], accA[(ii + 2) % 7], h2A);                   // d=5: h2 (dy=+2)
        MUL2(accB[(ii + 2) % 7], accB[(ii + 2) % 7], h2B);

        if (ii >= 6) {                                                        // d=6: t, emit
            u64 aA = accA[(ii + 1) % 7], aB = accB[(ii + 1) % 7];
            MUL2(aA, aA, T2);
            MUL2(aB, aB, T3);
            // m = 1 - a  (a = prod of factors in [0,1] -> m in [0,1], no clip needed)
            u64 mA, mB;
            FMA2(mA, aA, NEG2, ONE2);
            FMA2(mB, aB, NEG2, ONE2);
            u64 mwA, mwB;
            MUL2(mwA, mA, W2);
            MUL2(mwB, mB, W2);

            const int y = y0 + ii - 6;
            ulonglong2 xv = *(const ulonglong2*)(base + y * Ww + c0);
            u64 oA, oB;
            FMA2(oA, xv.x, IW2, mwA);    // 0.76*x + 0.24*m
            FMA2(oB, xv.y, IW2, mwB);

            float o0, o1, o2, o3;
            UNPACK2F(o0, o1, oA);
            UNPACK2F(o2, o3, oB);
            float4 o;
            o.x = fminf(fmaxf(o0, 0.f), 1.f);
            o.y = fminf(fmaxf(o1, 0.f), 1.f);
            o.z = fminf(fmaxf(o2, 0.f), 1.f);
            o.w = fminf(fmaxf(o3, 0.f), 1.f);
            *(float4*)(obase + y * Ww + c0) = o;
        }

        cur = nxt;
    }
}

extern "C" void kernel_launch(void* const* d_in, const int* in_sizes, int n_in,
                              void* d_out, int out_size)
{
    (void)in_sizes; (void)n_in; (void)out_size;
    const float* x = (const float*)d_in[0];   // (16,1,512,512) fp32; d_in[1] = i (fixed 30)
    float* o = (float*)d_out;
    // 4096 warps total: 16 imgs * 64 row-chunks * 4 column-quadrants
    morph_kernel<<<512, 256>>>(x, o);
}

// round 5
// speedup vs baseline: 1.1910x; 1.1910x over previous
#include <cuda_runtime.h>

// MorphologicalDegradation, i=30 fixed: k=7 circular SE, dilation, weight=0.24.
//   out = clip(0.76*x + 0.24*(1 - prod_taps(1 - x_shift)), 0, 1)
// Row decomposition (half-widths by dy): {0,2,2,3,2,2,0}:
//   out(y) = f( t(y-3) * h2(y-2) * h2(y-1) * h3(y) * h2(y+1) * h2(y+2) * t(y+3) )
//
// R5: back to scalar math (R4 f32x2 regressed: mov.b64 ALU overhead + reg pairing).
// Two latency fixes:
//  (a) ROUT=7 -> 74 chunks -> 4736 warps = 592 blocks = exactly 4 blocks x 148 SMs
//      (R3's 512 blocks filled only 86% of the 592 resident slots -> occ 37.6%).
//  (b) depth-2 prefetch of the center (M) row: load->use distance ~2 bodies
//      > L2 hit latency (234-262cyc). M lines also cover most L/R halo lines,
//      so L/R stay depth-1 (+4 regs only).

static constexpr int Hh     = 512;
static constexpr int Ww     = 512;
static constexpr int ROUT   = 7;             // output rows per warp-chunk
static constexpr int CHUNKS = 74;            // ceil(512/7); last chunk partially masked
static constexpr int ITERS  = ROUT + 6;      // 13 input rows streamed

__device__ __forceinline__ float4 zero4() { return make_float4(0.f, 0.f, 0.f, 0.f); }

__global__ void __launch_bounds__(256, 4)
morph_kernel(const float* __restrict__ x, float* __restrict__ out)
{
    const int gt    = blockIdx.x * 256 + threadIdx.x;
    const int gw    = gt >> 5;            // global warp id, 0..4735
    const int ln    = gt & 31;
    const int wp    = gw & 3;             // column quadrant (128 cols each)
    const int gwq   = gw >> 2;            // 0..1183
    const int chunk = gwq % CHUNKS;       // row chunk
    const int img   = gwq / CHUNKS;       // 16 images

    const int c0 = wp * 128 + ln * 4;     // first of 4 owned columns
    const int y0 = chunk * ROUT;

    const float* base  = x   + img * (Hh * Ww);
    float*       obase = out + img * (Hh * Ww);

    const float WGT  = 0.24f;
    const float IWGT = 1.0f - 0.24f;

    float4 acc[7];   // rotating accumulators (4 columns each)

    auto loadM = [&](int r) -> float4 {
        return ((unsigned)r < (unsigned)Hh) ? *(const float4*)(base + r * Ww + c0) : zero4();
    };
    auto loadLR = [&](int r, float4& L, float4& R) {
        if ((unsigned)r < (unsigned)Hh) {
            const float* row = base + r * Ww;
            L = (c0 >= 4)      ? *(const float4*)(row + c0 - 4) : zero4();
            R = (c0 <= Ww - 8) ? *(const float4*)(row + c0 + 4) : zero4();
        } else { L = zero4(); R = zero4(); }
    };

    // prologue: M at depth 2, L/R at depth 1
    float4 Mc = loadM(y0 - 3);
    float4 Mn = loadM(y0 - 2);
    float4 Lc, Rc;
    loadLR(y0 - 3, Lc, Rc);

#pragma unroll
    for (int ii = 0; ii < ITERS; ++ii) {
        const int r = y0 - 3 + ii;

        // prefetch: center row depth 2, halos depth 1
        float4 Mn2 = (ii + 2 < ITERS) ? loadM(r + 2) : zero4();
        float4 Ln, Rn;
        if (ii + 1 < ITERS) loadLR(r + 1, Ln, Rn);
        else                { Ln = zero4(); Rn = zero4(); }

        // reload raw x for the emit row early (L1 hit; loaded 3 iters ago)
        const int y = y0 + ii - 6;
        const bool emit = (ii >= 6) && (y < Hh);
        float4 xv;
        if (emit) xv = *(const float4*)(base + y * Ww + c0);

        // t window: t[1..10] used; t[i] is column c0-4+i
        float t[12];
        t[0]  = 1.f - Lc.x; t[1]  = 1.f - Lc.y; t[2]  = 1.f - Lc.z; t[3]  = 1.f - Lc.w;
        t[4]  = 1.f - Mc.x; t[5]  = 1.f - Mc.y; t[6]  = 1.f - Mc.z; t[7]  = 1.f - Mc.w;
        t[8]  = 1.f - Rc.x; t[9]  = 1.f - Rc.y; t[10] = 1.f - Rc.z; t[11] = 1.f - Rc.w;

        float h2[4], h3[4], tm[4];
#pragma unroll
        for (int j = 0; j < 4; ++j) {
            float p = t[2 + j] * t[3 + j];
            p *= t[4 + j];
            p *= t[5 + j];
            p *= t[6 + j];
            h2[j] = p;
            h3[j] = p * t[1 + j] * t[7 + j];
            tm[j] = t[4 + j];
        }

        // distance d from pending output's start; slot = (ii - d) % 7 (static after unroll)
        acc[ii % 7] = make_float4(tm[0], tm[1], tm[2], tm[3]);            // d=0: t (dy=-3)
        { float4& a = acc[(ii + 6) % 7];                                  // d=1: h2 (dy=-2)
          a.x *= h2[0]; a.y *= h2[1]; a.z *= h2[2]; a.w *= h2[3]; }
        { float4& a = acc[(ii + 5) % 7];                                  // d=2: h2 (dy=-1)
          a.x *= h2[0]; a.y *= h2[1]; a.z *= h2[2]; a.w *= h2[3]; }
        { float4& a = acc[(ii + 4) % 7];                                  // d=3: h3 (dy=0)
          a.x *= h3[0]; a.y *= h3[1]; a.z *= h3[2]; a.w *= h3[3]; }
        { float4& a = acc[(ii + 3) % 7];                                  // d=4: h2 (dy=+1)
          a.x *= h2[0]; a.y *= h2[1]; a.z *= h2[2]; a.w *= h2[3]; }
        { float4& a = acc[(ii + 2) % 7];                                  // d=5: h2 (dy=+2)
          a.x *= h2[0]; a.y *= h2[1]; a.z *= h2[2]; a.w *= h2[3]; }

        if (emit) {                                                       // d=6: t (dy=+3)
            float4 a = acc[(ii + 1) % 7];
            a.x *= tm[0]; a.y *= tm[1]; a.z *= tm[2]; a.w *= tm[3];

            float4 o;
            float m;
            m   = 1.f - a.x;   // a in [0,1] -> m in [0,1], no extra clip needed
            o.x = fminf(fmaxf(IWGT * xv.x + WGT * m, 0.f), 1.f);
            m   = 1.f - a.y;
            o.y = fminf(fmaxf(IWGT * xv.y + WGT * m, 0.f), 1.f);
            m   = 1.f - a.z;
            o.z = fminf(fmaxf(IWGT * xv.z + WGT * m, 0.f), 1.f);
            m   = 1.f - a.w;
            o.w = fminf(fmaxf(IWGT * xv.w + WGT * m, 0.f), 1.f);

            *(float4*)(obase + y * Ww + c0) = o;
        }

        Lc = Ln; Rc = Rn; Mc = Mn; Mn = Mn2;
    }
}

extern "C" void kernel_launch(void* const* d_in, const int* in_sizes, int n_in,
                              void* d_out, int out_size)
{
    (void)in_sizes; (void)n_in; (void)out_size;
    const float* x = (const float*)d_in[0];   // (16,1,512,512) fp32; d_in[1] = i (fixed 30)
    float* o = (float*)d_out;
    // 4736 warps = 16 imgs * 74 row-chunks * 4 column-quadrants
    //            = 592 blocks = exactly 4 resident blocks x 148 SMs (one full wave)
    morph_kernel<<<592, 256>>>(x, o);
}